// round 13
// baseline (speedup 1.0000x reference)
#include <cuda_runtime.h>
#include <cuda_fp16.h>

#define NMAX 100000
#define EMAX 3300000   // E + N self loops
#define FIN 512
#define HD  64
#define NITER 10
#define ALPHAF 0.1f
#define SCANB 1024
#define MAXBLK 128     // ceil(NMAX/SCANB) = 98

// ---------------- scratch (device globals; no allocation allowed) ------------
__device__ uint4 g_hv [NMAX * HD / 8];   // MLP output h (fp16); also z_0
__device__ uint4 g_z0v[NMAX * HD / 8];   // ping (fp16)
__device__ uint4 g_z1v[NMAX * HD / 8];   // pong (fp16)
__device__ float g_deg[NMAX];            // degree -> dinv (in place)
__device__ int   g_cnt[NMAX];            // in-degree histogram (by col)
__device__ int   g_rowptr[NMAX + 1];     // CSR row pointer (by destination)
__device__ int   g_cursor[NMAX];         // scatter cursors
__device__ unsigned g_edgep[EMAX];       // CSR: src(17b) | fp16-weight sans sign(15b)
__device__ int   g_bsum[MAXBLK];         // block sums for scan
__device__ unsigned g_barcnt;            // prop grid-barrier counter
__device__ unsigned g_scanbar;           // scan grid-barrier counter

// ---------------- preprocessing kernels --------------------------------------

__global__ void zero_kernel(int N) {
    int i = blockIdx.x * blockDim.x + threadIdx.x;
    int stride = gridDim.x * blockDim.x;
    if (i == 0) { g_barcnt = 0; g_scanbar = 0; }
    for (; i < N; i += stride) { g_deg[i] = 0.0f; g_cnt[i] = 0; }
}

__global__ void degcnt_kernel(const int* __restrict__ ei,
                              const float* __restrict__ ew, int E, int N) {
    int i2 = (blockIdx.x * blockDim.x + threadIdx.x) * 2;
    int stride = gridDim.x * blockDim.x * 2;
    int total = E + N;
    for (; i2 < total; i2 += stride) {
        #pragma unroll
        for (int q = 0; q < 2; q++) {
            int i = i2 + q;
            if (i >= total) break;
            int r, c; float w;
            if (i < E) { r = ei[i]; c = ei[E + i]; w = ew[i]; }
            else       { r = c = i - E; w = 1.0f; }
            atomicAdd(&g_deg[r], w);
            atomicAdd(&g_cnt[c], 1);
        }
    }
}

// ---- fused scan: dinv conversion + 3-phase exclusive scan in ONE kernel ------
__global__ void scan_fused(int N, int total, int nblk) {
    __shared__ int sdata[SCANB];
    __shared__ int bpref[MAXBLK];
    int tid = threadIdx.x;
    int bid = blockIdx.x;
    int i = bid * SCANB + tid;

    if (i < N) {
        float d = g_deg[i];
        g_deg[i] = (d > 0.0f) ? rsqrtf(d) : 0.0f;
    }
    int v = (i < N) ? g_cnt[i] : 0;
    sdata[tid] = v;
    __syncthreads();
    #pragma unroll
    for (int off = 1; off < SCANB; off <<= 1) {
        int t = (tid >= off) ? sdata[tid - off] : 0;
        __syncthreads();
        sdata[tid] += t;
        __syncthreads();
    }
    int local_excl = sdata[tid] - v;
    if (tid == SCANB - 1) g_bsum[bid] = sdata[tid];

    __syncthreads();
    if (tid == 0) {
        __threadfence();
        atomicAdd(&g_scanbar, 1u);
        while (atomicAdd(&g_scanbar, 0u) < (unsigned)nblk) __nanosleep(64);
    }
    __syncthreads();

    int bv = (tid < nblk) ? g_bsum[tid] : 0;
    if (tid < MAXBLK) bpref[tid] = bv;
    __syncthreads();
    #pragma unroll
    for (int off = 1; off < MAXBLK; off <<= 1) {
        int t = 0;
        if (tid < MAXBLK && tid >= off) t = bpref[tid - off];
        __syncthreads();
        if (tid < MAXBLK) bpref[tid] += t;
        __syncthreads();
    }
    int base = (bid > 0) ? bpref[bid - 1] : 0;

    if (i < N) {
        int r = local_excl + base;
        g_rowptr[i] = r;
        g_cursor[i] = r;
    }
    if (i == N - 1) g_rowptr[N] = total;
}

// store packed (src<<15 | fp16weight sans sign); weights nonneg
__global__ void scatter_kernel(const int* __restrict__ ei,
                               const float* __restrict__ ew, int E, int N) {
    int i2 = (blockIdx.x * blockDim.x + threadIdx.x) * 2;
    int stride = gridDim.x * blockDim.x * 2;
    int total = E + N;
    for (; i2 < total; i2 += stride) {
        #pragma unroll
        for (int q = 0; q < 2; q++) {
            int i = i2 + q;
            if (i >= total) break;
            int r, c; float w;
            if (i < E) { r = ei[i]; c = ei[E + i]; w = ew[i]; }
            else       { r = c = i - E; w = 1.0f; }
            float wn = g_deg[r] * w;          // g_deg holds dinv; wn >= 0
            unsigned hw = (unsigned)__half_as_ushort(__float2half_rn(wn)) & 0x7fffu;
            int pos = atomicAdd(&g_cursor[c], 1);
            g_edgep[pos] = ((unsigned)r << 15) | hw;
        }
    }
}

// ---------------- MLP via tensor cores + ldmatrix ----------------------------
// smem strides tuned so 8 consecutive rows land on all 32 banks (ldmatrix
// conflict-free): 80B = 20 banks/row, 144B = 36 banks/row.
#define AS_STRIDE 40   // halfs; 80 B/row
#define TS_STRIDE 72   // halfs; 144 B/row

__device__ __forceinline__ void mma16816(float c[4],
                                         unsigned a0, unsigned a1, unsigned a2, unsigned a3,
                                         unsigned b0, unsigned b1) {
    asm volatile(
        "mma.sync.aligned.m16n8k16.row.col.f32.f16.f16.f32 "
        "{%0,%1,%2,%3}, {%4,%5,%6,%7}, {%8,%9}, {%0,%1,%2,%3};"
        : "+f"(c[0]), "+f"(c[1]), "+f"(c[2]), "+f"(c[3])
        : "r"(a0), "r"(a1), "r"(a2), "r"(a3), "r"(b0), "r"(b1));
}

__device__ __forceinline__ void ldm_x4(unsigned &r0, unsigned &r1,
                                       unsigned &r2, unsigned &r3, const void* p) {
    unsigned addr = (unsigned)__cvta_generic_to_shared(p);
    asm volatile("ldmatrix.sync.aligned.m8n8.x4.shared.b16 {%0,%1,%2,%3}, [%4];"
                 : "=r"(r0), "=r"(r1), "=r"(r2), "=r"(r3) : "r"(addr));
}

__global__ __launch_bounds__(256) void mlp_kernel(
    const float* __restrict__ x,  const float* __restrict__ W0,
    const float* __restrict__ b0, const float* __restrict__ W1,
    const float* __restrict__ b1, int N)
{
    __shared__ __half As[128][AS_STRIDE];
    __shared__ __half Bs[64][AS_STRIDE];
    __shared__ __half Ts[128][TS_STRIDE];
    __shared__ __half W1s[64][TS_STRIDE];
    __shared__ float b0s[64];
    __shared__ float b1s[64];

    int tid  = threadIdx.x;
    int wid  = tid >> 5;
    int lane = tid & 31;
    int g = lane >> 2;
    int t = lane & 3;
    int wr0 = wid * 16;
    int row0 = blockIdx.x * 128;

    // ldmatrix lane-address components
    int arow = (lane & 15);             // row within 16-row strip
    int akof = (lane >> 4) << 3;        // 0 or 8 (k-half)
    int bn   = lane & 7;                // n within 8
    int bsel = (lane >> 4) & 1;         // which nt of the pair
    int bkof = lane & 8;                // 0 or 8 (k-half)

    for (int i = tid; i < 64 * 64; i += 256) {
        int k = i >> 6, n = i & 63;
        W1s[n][k] = __float2half(W1[i]);
    }
    if (tid < 64) { b0s[tid] = b0[tid]; b1s[tid] = b1[tid]; }

    float c1a[8][4] = {};

    int lr = tid >> 1;
    int lq = tid & 1;
    bool rowok = (row0 + lr) < N;
    const float* xrow = x + (size_t)(row0 + lr) * FIN;

    for (int k0 = 0; k0 < FIN; k0 += 32) {
        #pragma unroll
        for (int jj = 0; jj < 4; jj++) {
            float4 v = rowok ? *(const float4*)(xrow + k0 + 16 * lq + 4 * jj)
                             : make_float4(0.f, 0.f, 0.f, 0.f);
            *(__half2*)&As[lr][16 * lq + 4 * jj]     = __floats2half2_rn(v.x, v.y);
            *(__half2*)&As[lr][16 * lq + 4 * jj + 2] = __floats2half2_rn(v.z, v.w);
        }
        for (int i = tid; i < 32 * 64; i += 256) {
            int kr = i >> 6, nc = i & 63;
            Bs[nc][kr] = __float2half(W0[(size_t)(k0 + kr) * HD + nc]);
        }
        __syncthreads();

        #pragma unroll
        for (int kk = 0; kk < 32; kk += 16) {
            unsigned a0, a1, a2, a3;
            ldm_x4(a0, a1, a2, a3, &As[wr0 + arow][kk + akof]);
            #pragma unroll
            for (int nt = 0; nt < 8; nt += 2) {
                unsigned bb0, bb1, bb2, bb3;
                ldm_x4(bb0, bb1, bb2, bb3,
                       &Bs[(nt + bsel) * 8 + bn][kk + bkof]);
                mma16816(c1a[nt],     a0, a1, a2, a3, bb0, bb1);
                mma16816(c1a[nt + 1], a0, a1, a2, a3, bb2, bb3);
            }
        }
        __syncthreads();
    }

    #pragma unroll
    for (int nt = 0; nt < 8; nt++) {
        int col = nt * 8 + 2 * t;
        float v0 = fmaxf(c1a[nt][0] + b0s[col], 0.f);
        float v1 = fmaxf(c1a[nt][1] + b0s[col + 1], 0.f);
        float v2 = fmaxf(c1a[nt][2] + b0s[col], 0.f);
        float v3 = fmaxf(c1a[nt][3] + b0s[col + 1], 0.f);
        *(__half2*)&Ts[wr0 + g][col]     = __floats2half2_rn(v0, v1);
        *(__half2*)&Ts[wr0 + g + 8][col] = __floats2half2_rn(v2, v3);
    }
    __syncthreads();

    float c2a[8][4] = {};
    #pragma unroll
    for (int kk = 0; kk < 64; kk += 16) {
        unsigned a0, a1, a2, a3;
        ldm_x4(a0, a1, a2, a3, &Ts[wr0 + arow][kk + akof]);
        #pragma unroll
        for (int nt = 0; nt < 8; nt += 2) {
            unsigned bb0, bb1, bb2, bb3;
            ldm_x4(bb0, bb1, bb2, bb3,
                   &W1s[(nt + bsel) * 8 + bn][kk + bkof]);
            mma16816(c2a[nt],     a0, a1, a2, a3, bb0, bb1);
            mma16816(c2a[nt + 1], a0, a1, a2, a3, bb2, bb3);
        }
    }

    __half* gh = (__half*)g_hv;
    int r0 = row0 + wr0 + g;
    int r1 = r0 + 8;
    #pragma unroll
    for (int nt = 0; nt < 8; nt++) {
        int col = nt * 8 + 2 * t;
        __half2 lo = __floats2half2_rn(c2a[nt][0] + b1s[col], c2a[nt][1] + b1s[col + 1]);
        __half2 hi = __floats2half2_rn(c2a[nt][2] + b1s[col], c2a[nt][3] + b1s[col + 1]);
        if (r0 < N) *(__half2*)(gh + (size_t)r0 * HD + col) = lo;
        if (r1 < N) *(__half2*)(gh + (size_t)r1 * HD + col) = hi;
    }
}

// ---------------- persistent propagation --------------------------------------
__device__ __forceinline__ void unpack_edge(unsigned p, int &s, float &w) {
    s = (int)(p >> 15);
    w = __half2float(__ushort_as_half((unsigned short)(p & 0x7fffu)));
}

__global__ __launch_bounds__(256) void prop_persist(float* __restrict__ dout,
                                                    int N, int nblocks)
{
    int tid  = threadIdx.x;
    int lane = tid & 15;
    int lwid = tid >> 4;
    const __half* gh = (const __half*)g_hv;

    #pragma unroll 1
    for (int it = 0; it < NITER; it++) {
        const __half* zin = (it == 0) ? gh
                           : (const __half*)((it & 1) ? g_z0v : g_z1v);
        __half* zout16 = (__half*)((it & 1) ? g_z1v : g_z0v);

        for (int node = blockIdx.x * 16 + lwid; node < N; node += nblocks * 16) {
            int start = __ldg(&g_rowptr[node]);
            int end   = __ldg(&g_rowptr[node + 1]);

            float acc[4] = {};
            int e = start;
            for (; e + 4 <= end; e += 4) {
                unsigned pa = __ldg(&g_edgep[e]);
                unsigned pb = __ldg(&g_edgep[e + 1]);
                unsigned pc = __ldg(&g_edgep[e + 2]);
                unsigned pd = __ldg(&g_edgep[e + 3]);
                int sa, sb, sc, sd; float wa, wb, wc, wd;
                unpack_edge(pa, sa, wa); unpack_edge(pb, sb, wb);
                unpack_edge(pc, sc, wc); unpack_edge(pd, sd, wd);
                uint2 va = __ldcg((const uint2*)(zin + (size_t)sa * HD + 4 * lane));
                uint2 vb = __ldcg((const uint2*)(zin + (size_t)sb * HD + 4 * lane));
                uint2 vc = __ldcg((const uint2*)(zin + (size_t)sc * HD + 4 * lane));
                uint2 vd = __ldcg((const uint2*)(zin + (size_t)sd * HD + 4 * lane));
                float2 a0 = __half22float2(*(__half2*)&va.x);
                float2 a1 = __half22float2(*(__half2*)&va.y);
                float2 b0 = __half22float2(*(__half2*)&vb.x);
                float2 b1 = __half22float2(*(__half2*)&vb.y);
                float2 c0 = __half22float2(*(__half2*)&vc.x);
                float2 c1 = __half22float2(*(__half2*)&vc.y);
                float2 d0 = __half22float2(*(__half2*)&vd.x);
                float2 d1 = __half22float2(*(__half2*)&vd.y);
                acc[0] += wa * a0.x + wb * b0.x + wc * c0.x + wd * d0.x;
                acc[1] += wa * a0.y + wb * b0.y + wc * c0.y + wd * d0.y;
                acc[2] += wa * a1.x + wb * b1.x + wc * c1.x + wd * d1.x;
                acc[3] += wa * a1.y + wb * b1.y + wc * c1.y + wd * d1.y;
            }
            for (; e < end; e++) {
                unsigned pa = __ldg(&g_edgep[e]);
                int sa; float wa;
                unpack_edge(pa, sa, wa);
                uint2 va = __ldcg((const uint2*)(zin + (size_t)sa * HD + 4 * lane));
                float2 a0 = __half22float2(*(__half2*)&va.x);
                float2 a1 = __half22float2(*(__half2*)&va.y);
                acc[0] += wa * a0.x;
                acc[1] += wa * a0.y;
                acc[2] += wa * a1.x;
                acc[3] += wa * a1.y;
            }

            float s = (1.0f - ALPHAF) * __ldg(&g_deg[node]);

            uint2 hv = __ldg((const uint2*)(gh + (size_t)node * HD + 4 * lane));
            float2 h0 = __half22float2(*(__half2*)&hv.x);
            float2 h1 = __half22float2(*(__half2*)&hv.y);
            float o0 = s * acc[0] + ALPHAF * h0.x;
            float o1 = s * acc[1] + ALPHAF * h0.y;
            float o2 = s * acc[2] + ALPHAF * h1.x;
            float o3 = s * acc[3] + ALPHAF * h1.y;

            if (it == NITER - 1) {
                *(float4*)(dout + (size_t)node * HD + 4 * lane) =
                    make_float4(o0, o1, o2, o3);
            } else {
                __half2 p0 = __float22half2_rn(make_float2(o0, o1));
                __half2 p1 = __float22half2_rn(make_float2(o2, o3));
                uint2 u;
                u.x = *(unsigned int*)&p0;
                u.y = *(unsigned int*)&p1;
                *(uint2*)(zout16 + (size_t)node * HD + 4 * lane) = u;
            }
        }

        if (it < NITER - 1) {
            __syncthreads();
            if (tid == 0) {
                __threadfence();
                atomicAdd(&g_barcnt, 1u);
                unsigned target = (unsigned)(it + 1) * (unsigned)nblocks;
                while (atomicAdd(&g_barcnt, 0u) < target) __nanosleep(128);
            }
            __syncthreads();
        }
    }
}

// ---------------- launcher ----------------------------------------------------
extern "C" void kernel_launch(void* const* d_in, const int* in_sizes, int n_in,
                              void* d_out, int out_size)
{
    const float* x  = (const float*)d_in[0];
    const int*   ei = (const int*)  d_in[1];
    const float* ew = (const float*)d_in[2];
    const float* W0 = (const float*)d_in[3];
    const float* b0 = (const float*)d_in[4];
    const float* W1 = (const float*)d_in[5];
    const float* b1 = (const float*)d_in[6];
    float* out = (float*)d_out;

    int N = in_sizes[0] / FIN;
    int E = in_sizes[2];
    int total = E + N;

    int tpb = 256;
    int nblk = (N + tpb - 1) / tpb;
    int eblk = ((total + 1) / 2 + tpb - 1) / tpb;
    if (eblk > 4096) eblk = 4096;
    int sblk = (N + SCANB - 1) / SCANB;

    int dev = 0, nsm = 0, bpm = 0;
    cudaGetDevice(&dev);
    cudaDeviceGetAttribute(&nsm, cudaDevAttrMultiProcessorCount, dev);
    cudaOccupancyMaxActiveBlocksPerMultiprocessor(&bpm, prop_persist, tpb, 0);
    if (bpm < 1) bpm = 1;
    int pgrid = nsm * bpm;
    int maxuseful = (N + 15) / 16;
    if (pgrid > maxuseful) pgrid = maxuseful;

    // fork: MLP (independent of CSR build) on a side stream
    cudaStream_t s2;
    cudaStreamCreateWithFlags(&s2, cudaStreamNonBlocking);
    cudaEvent_t evFork, evJoin;
    cudaEventCreateWithFlags(&evFork, cudaEventDisableTiming);
    cudaEventCreateWithFlags(&evJoin, cudaEventDisableTiming);

    cudaEventRecord(evFork, 0);
    cudaStreamWaitEvent(s2, evFork, 0);
    mlp_kernel<<<(N + 127) / 128, 256, 0, s2>>>(x, W0, b0, W1, b1, N);
    cudaEventRecord(evJoin, s2);

    // CSR build on the main (capture) stream
    zero_kernel<<<nblk, tpb>>>(N);
    degcnt_kernel<<<eblk, tpb>>>(ei, ew, E, N);
    scan_fused<<<sblk, SCANB>>>(N, total, sblk);
    scatter_kernel<<<eblk, tpb>>>(ei, ew, E, N);

    cudaStreamWaitEvent(0, evJoin, 0);

    prop_persist<<<pgrid, tpb>>>(out, N, pgrid);
    // s2/events intentionally not destroyed: destroying objects referenced by
    // an in-progress capture invalidates the graph; leaks host handles only.
}

// round 14
// speedup vs baseline: 1.0493x; 1.0493x over previous
#include <cuda_runtime.h>
#include <cuda_fp16.h>

#define NMAX 100000
#define EMAX 3300000   // E + N self loops
#define FIN 512
#define HD  64
#define NITER 10
#define ALPHAF 0.1f
#define SCANB 1024
#define MAXBLK 128     // ceil(NMAX/SCANB) = 98

// ---------------- scratch (device globals; no allocation allowed) ------------
__device__ uint4 g_hv [NMAX * HD / 8];   // MLP output h (fp16); also z_0
__device__ uint4 g_z0v[NMAX * HD / 8];   // ping (fp16)
__device__ uint4 g_z1v[NMAX * HD / 8];   // pong (fp16)
__device__ float g_deg[NMAX];            // degree -> dinv (in place)
__device__ int   g_cnt[NMAX];            // in-degree histogram (by col)
__device__ int   g_rowptr[NMAX + 1];     // CSR row pointer (by destination)
__device__ int   g_cursor[NMAX];         // scatter cursors
__device__ int2  g_edge[EMAX];           // CSR: {src, bits of dinv[src]*w}
__device__ int   g_bsum[MAXBLK];         // block sums for scan
__device__ unsigned g_barcnt;            // prop grid-barrier counter
__device__ unsigned g_scanbar;           // scan grid-barrier counter

// ---------------- preprocessing kernels --------------------------------------

__global__ void zero_kernel(int N) {
    int i = blockIdx.x * blockDim.x + threadIdx.x;
    int stride = gridDim.x * blockDim.x;
    if (i == 0) { g_barcnt = 0; g_scanbar = 0; }
    for (; i < N; i += stride) { g_deg[i] = 0.0f; g_cnt[i] = 0; }
}

__global__ void degcnt_kernel(const int* __restrict__ ei,
                              const float* __restrict__ ew, int E, int N) {
    int i2 = (blockIdx.x * blockDim.x + threadIdx.x) * 2;
    int stride = gridDim.x * blockDim.x * 2;
    int total = E + N;
    for (; i2 < total; i2 += stride) {
        #pragma unroll
        for (int q = 0; q < 2; q++) {
            int i = i2 + q;
            if (i >= total) break;
            int r, c; float w;
            if (i < E) { r = ei[i]; c = ei[E + i]; w = ew[i]; }
            else       { r = c = i - E; w = 1.0f; }
            atomicAdd(&g_deg[r], w);
            atomicAdd(&g_cnt[c], 1);
        }
    }
}

// ---- fused scan: dinv conversion + 3-phase exclusive scan in ONE kernel ------
__global__ void scan_fused(int N, int total, int nblk) {
    __shared__ int sdata[SCANB];
    __shared__ int bpref[MAXBLK];
    int tid = threadIdx.x;
    int bid = blockIdx.x;
    int i = bid * SCANB + tid;

    if (i < N) {
        float d = g_deg[i];
        g_deg[i] = (d > 0.0f) ? rsqrtf(d) : 0.0f;
    }
    int v = (i < N) ? g_cnt[i] : 0;
    sdata[tid] = v;
    __syncthreads();
    #pragma unroll
    for (int off = 1; off < SCANB; off <<= 1) {
        int t = (tid >= off) ? sdata[tid - off] : 0;
        __syncthreads();
        sdata[tid] += t;
        __syncthreads();
    }
    int local_excl = sdata[tid] - v;
    if (tid == SCANB - 1) g_bsum[bid] = sdata[tid];

    __syncthreads();
    if (tid == 0) {
        __threadfence();
        atomicAdd(&g_scanbar, 1u);
        while (atomicAdd(&g_scanbar, 0u) < (unsigned)nblk) __nanosleep(64);
    }
    __syncthreads();

    int bv = (tid < nblk) ? g_bsum[tid] : 0;
    if (tid < MAXBLK) bpref[tid] = bv;
    __syncthreads();
    #pragma unroll
    for (int off = 1; off < MAXBLK; off <<= 1) {
        int t = 0;
        if (tid < MAXBLK && tid >= off) t = bpref[tid - off];
        __syncthreads();
        if (tid < MAXBLK) bpref[tid] += t;
        __syncthreads();
    }
    int base = (bid > 0) ? bpref[bid - 1] : 0;

    if (i < N) {
        int r = local_excl + base;
        g_rowptr[i] = r;
        g_cursor[i] = r;
    }
    if (i == N - 1) g_rowptr[N] = total;
}

// store (src, dinv[src]*w) as int2; dinv[dst] applied once per node in prop
__global__ void scatter_kernel(const int* __restrict__ ei,
                               const float* __restrict__ ew, int E, int N) {
    int i2 = (blockIdx.x * blockDim.x + threadIdx.x) * 2;
    int stride = gridDim.x * blockDim.x * 2;
    int total = E + N;
    for (; i2 < total; i2 += stride) {
        #pragma unroll
        for (int q = 0; q < 2; q++) {
            int i = i2 + q;
            if (i >= total) break;
            int r, c; float w;
            if (i < E) { r = ei[i]; c = ei[E + i]; w = ew[i]; }
            else       { r = c = i - E; w = 1.0f; }
            float wn = g_deg[r] * w;          // g_deg holds dinv now
            int pos = atomicAdd(&g_cursor[c], 1);
            g_edge[pos] = make_int2(r, __float_as_int(wn));
        }
    }
}

// ---------------- MLP via tensor cores (mma.sync m16n8k16 f16->f32) ----------
// Stage 1 double-buffered: gmem loads for chunk c+1 issued before computing
// chunk c; register-staged; ONE syncthreads per chunk.
#define AS_STRIDE 36
#define TS_STRIDE 68

__device__ __forceinline__ void mma16816(float c[4],
                                         unsigned a0, unsigned a1, unsigned a2, unsigned a3,
                                         unsigned b0, unsigned b1) {
    asm volatile(
        "mma.sync.aligned.m16n8k16.row.col.f32.f16.f16.f32 "
        "{%0,%1,%2,%3}, {%4,%5,%6,%7}, {%8,%9}, {%0,%1,%2,%3};"
        : "+f"(c[0]), "+f"(c[1]), "+f"(c[2]), "+f"(c[3])
        : "r"(a0), "r"(a1), "r"(a2), "r"(a3), "r"(b0), "r"(b1));
}

__global__ __launch_bounds__(256) void mlp_kernel(
    const float* __restrict__ x,  const float* __restrict__ W0,
    const float* __restrict__ b0, const float* __restrict__ W1,
    const float* __restrict__ b1, int N)
{
    __shared__ __half As[2][128][AS_STRIDE];
    __shared__ __half Bs[2][64][AS_STRIDE];
    __shared__ __half Ts[128][TS_STRIDE];
    __shared__ __half W1s[64][TS_STRIDE];
    __shared__ float b0s[64];
    __shared__ float b1s[64];

    int tid  = threadIdx.x;
    int wid  = tid >> 5;
    int lane = tid & 31;
    int g = lane >> 2;
    int t = lane & 3;
    int wr0 = wid * 16;
    int row0 = blockIdx.x * 128;

    for (int i = tid; i < 64 * 64; i += 256) {
        int k = i >> 6, n = i & 63;
        W1s[n][k] = __float2half(W1[i]);
    }
    if (tid < 64) { b0s[tid] = b0[tid]; b1s[tid] = b1[tid]; }

    float c1a[8][4] = {};

    // loader mappings (as R12)
    int lr = tid >> 1;            // x row 0..127
    int lq = tid & 1;             // 16-float half of the 32-k chunk
    bool rowok = (row0 + lr) < N;
    const float* xrow = x + (size_t)(row0 + lr) * FIN;
    int wkr = tid >> 6;           // base W0 k-row step (8 scalars per thread)
    int wnc = tid & 63;

    float4 xreg[4];
    float  wreg[8];

    // prologue: load chunk 0 into registers
    #pragma unroll
    for (int jj = 0; jj < 4; jj++)
        xreg[jj] = rowok ? *(const float4*)(xrow + 16 * lq + 4 * jj)
                         : make_float4(0.f, 0.f, 0.f, 0.f);
    #pragma unroll
    for (int q = 0; q < 8; q++)
        wreg[q] = W0[(size_t)(wkr + 4 * q) * HD + wnc];

    // store chunk 0 to buffer 0
    #pragma unroll
    for (int jj = 0; jj < 4; jj++) {
        *(__half2*)&As[0][lr][16 * lq + 4 * jj]     = __floats2half2_rn(xreg[jj].x, xreg[jj].y);
        *(__half2*)&As[0][lr][16 * lq + 4 * jj + 2] = __floats2half2_rn(xreg[jj].z, xreg[jj].w);
    }
    #pragma unroll
    for (int q = 0; q < 8; q++)
        Bs[0][wnc][wkr + 4 * q] = __float2half(wreg[q]);
    __syncthreads();

    #pragma unroll 1
    for (int c = 0; c < FIN / 32; c++) {
        int buf = c & 1;
        // issue gmem loads for chunk c+1 (latency overlaps with MMAs below)
        if (c + 1 < FIN / 32) {
            int k0 = (c + 1) * 32;
            #pragma unroll
            for (int jj = 0; jj < 4; jj++)
                xreg[jj] = rowok ? *(const float4*)(xrow + k0 + 16 * lq + 4 * jj)
                                 : make_float4(0.f, 0.f, 0.f, 0.f);
            #pragma unroll
            for (int q = 0; q < 8; q++)
                wreg[q] = W0[(size_t)(k0 + wkr + 4 * q) * HD + wnc];
        }

        // compute chunk c from buf
        #pragma unroll
        for (int kk = 0; kk < 32; kk += 16) {
            unsigned a0 = *(const unsigned*)&As[buf][wr0 + g][kk + 2 * t];
            unsigned a1 = *(const unsigned*)&As[buf][wr0 + g + 8][kk + 2 * t];
            unsigned a2 = *(const unsigned*)&As[buf][wr0 + g][kk + 2 * t + 8];
            unsigned a3 = *(const unsigned*)&As[buf][wr0 + g + 8][kk + 2 * t + 8];
            #pragma unroll
            for (int nt = 0; nt < 8; nt++) {
                unsigned bb0 = *(const unsigned*)&Bs[buf][nt * 8 + g][kk + 2 * t];
                unsigned bb1 = *(const unsigned*)&Bs[buf][nt * 8 + g][kk + 2 * t + 8];
                mma16816(c1a[nt], a0, a1, a2, a3, bb0, bb1);
            }
        }

        // stage chunk c+1 into the other buffer
        if (c + 1 < FIN / 32) {
            int nbuf = buf ^ 1;
            #pragma unroll
            for (int jj = 0; jj < 4; jj++) {
                *(__half2*)&As[nbuf][lr][16 * lq + 4 * jj]     = __floats2half2_rn(xreg[jj].x, xreg[jj].y);
                *(__half2*)&As[nbuf][lr][16 * lq + 4 * jj + 2] = __floats2half2_rn(xreg[jj].z, xreg[jj].w);
            }
            #pragma unroll
            for (int q = 0; q < 8; q++)
                Bs[nbuf][wnc][wkr + 4 * q] = __float2half(wreg[q]);
        }
        __syncthreads();
    }

    #pragma unroll
    for (int nt = 0; nt < 8; nt++) {
        int col = nt * 8 + 2 * t;
        float v0 = fmaxf(c1a[nt][0] + b0s[col], 0.f);
        float v1 = fmaxf(c1a[nt][1] + b0s[col + 1], 0.f);
        float v2 = fmaxf(c1a[nt][2] + b0s[col], 0.f);
        float v3 = fmaxf(c1a[nt][3] + b0s[col + 1], 0.f);
        *(__half2*)&Ts[wr0 + g][col]     = __floats2half2_rn(v0, v1);
        *(__half2*)&Ts[wr0 + g + 8][col] = __floats2half2_rn(v2, v3);
    }
    __syncthreads();

    float c2a[8][4] = {};
    #pragma unroll
    for (int kk = 0; kk < 64; kk += 16) {
        unsigned a0 = *(const unsigned*)&Ts[wr0 + g][kk + 2 * t];
        unsigned a1 = *(const unsigned*)&Ts[wr0 + g + 8][kk + 2 * t];
        unsigned a2 = *(const unsigned*)&Ts[wr0 + g][kk + 2 * t + 8];
        unsigned a3 = *(const unsigned*)&Ts[wr0 + g + 8][kk + 2 * t + 8];
        #pragma unroll
        for (int nt = 0; nt < 8; nt++) {
            unsigned bb0 = *(const unsigned*)&W1s[nt * 8 + g][kk + 2 * t];
            unsigned bb1 = *(const unsigned*)&W1s[nt * 8 + g][kk + 2 * t + 8];
            mma16816(c2a[nt], a0, a1, a2, a3, bb0, bb1);
        }
    }

    __half* gh = (__half*)g_hv;
    int r0 = row0 + wr0 + g;
    int r1 = r0 + 8;
    #pragma unroll
    for (int nt = 0; nt < 8; nt++) {
        int col = nt * 8 + 2 * t;
        __half2 lo = __floats2half2_rn(c2a[nt][0] + b1s[col], c2a[nt][1] + b1s[col + 1]);
        __half2 hi = __floats2half2_rn(c2a[nt][2] + b1s[col], c2a[nt][3] + b1s[col + 1]);
        if (r0 < N) *(__half2*)(gh + (size_t)r0 * HD + col) = lo;
        if (r1 < N) *(__half2*)(gh + (size_t)r1 * HD + col) = hi;
    }
}

// ---------------- persistent propagation (R12-proven) --------------------------
__global__ __launch_bounds__(256) void prop_persist(float* __restrict__ dout,
                                                    int N, int nblocks)
{
    int tid  = threadIdx.x;
    int lane = tid & 15;
    int lwid = tid >> 4;
    const __half* gh = (const __half*)g_hv;

    #pragma unroll 1
    for (int it = 0; it < NITER; it++) {
        const __half* zin = (it == 0) ? gh
                           : (const __half*)((it & 1) ? g_z0v : g_z1v);
        __half* zout16 = (__half*)((it & 1) ? g_z1v : g_z0v);

        for (int node = blockIdx.x * 16 + lwid; node < N; node += nblocks * 16) {
            int start = __ldg(&g_rowptr[node]);
            int end   = __ldg(&g_rowptr[node + 1]);

            float acc[4] = {};
            int e = start;
            for (; e + 4 <= end; e += 4) {
                int2 ea = __ldg(&g_edge[e]);
                int2 eb = __ldg(&g_edge[e + 1]);
                int2 ec = __ldg(&g_edge[e + 2]);
                int2 ed = __ldg(&g_edge[e + 3]);
                uint2 va = __ldcg((const uint2*)(zin + (size_t)ea.x * HD + 4 * lane));
                uint2 vb = __ldcg((const uint2*)(zin + (size_t)eb.x * HD + 4 * lane));
                uint2 vc = __ldcg((const uint2*)(zin + (size_t)ec.x * HD + 4 * lane));
                uint2 vd = __ldcg((const uint2*)(zin + (size_t)ed.x * HD + 4 * lane));
                float wa = __int_as_float(ea.y), wb = __int_as_float(eb.y);
                float wc = __int_as_float(ec.y), wd = __int_as_float(ed.y);
                float2 a0 = __half22float2(*(__half2*)&va.x);
                float2 a1 = __half22float2(*(__half2*)&va.y);
                float2 b0 = __half22float2(*(__half2*)&vb.x);
                float2 b1 = __half22float2(*(__half2*)&vb.y);
                float2 c0 = __half22float2(*(__half2*)&vc.x);
                float2 c1 = __half22float2(*(__half2*)&vc.y);
                float2 d0 = __half22float2(*(__half2*)&vd.x);
                float2 d1 = __half22float2(*(__half2*)&vd.y);
                acc[0] += wa * a0.x + wb * b0.x + wc * c0.x + wd * d0.x;
                acc[1] += wa * a0.y + wb * b0.y + wc * c0.y + wd * d0.y;
                acc[2] += wa * a1.x + wb * b1.x + wc * c1.x + wd * d1.x;
                acc[3] += wa * a1.y + wb * b1.y + wc * c1.y + wd * d1.y;
            }
            for (; e < end; e++) {
                int2 ea = __ldg(&g_edge[e]);
                uint2 va = __ldcg((const uint2*)(zin + (size_t)ea.x * HD + 4 * lane));
                float wa = __int_as_float(ea.y);
                float2 a0 = __half22float2(*(__half2*)&va.x);
                float2 a1 = __half22float2(*(__half2*)&va.y);
                acc[0] += wa * a0.x;
                acc[1] += wa * a0.y;
                acc[2] += wa * a1.x;
                acc[3] += wa * a1.y;
            }

            float s = (1.0f - ALPHAF) * __ldg(&g_deg[node]);

            uint2 hv = __ldg((const uint2*)(gh + (size_t)node * HD + 4 * lane));
            float2 h0 = __half22float2(*(__half2*)&hv.x);
            float2 h1 = __half22float2(*(__half2*)&hv.y);
            float o0 = s * acc[0] + ALPHAF * h0.x;
            float o1 = s * acc[1] + ALPHAF * h0.y;
            float o2 = s * acc[2] + ALPHAF * h1.x;
            float o3 = s * acc[3] + ALPHAF * h1.y;

            if (it == NITER - 1) {
                *(float4*)(dout + (size_t)node * HD + 4 * lane) =
                    make_float4(o0, o1, o2, o3);
            } else {
                __half2 p0 = __float22half2_rn(make_float2(o0, o1));
                __half2 p1 = __float22half2_rn(make_float2(o2, o3));
                uint2 u;
                u.x = *(unsigned int*)&p0;
                u.y = *(unsigned int*)&p1;
                *(uint2*)(zout16 + (size_t)node * HD + 4 * lane) = u;
            }
        }

        if (it < NITER - 1) {
            __syncthreads();
            if (tid == 0) {
                __threadfence();
                atomicAdd(&g_barcnt, 1u);
                unsigned target = (unsigned)(it + 1) * (unsigned)nblocks;
                while (atomicAdd(&g_barcnt, 0u) < target) __nanosleep(128);
            }
            __syncthreads();
        }
    }
}

// ---------------- launcher ----------------------------------------------------
extern "C" void kernel_launch(void* const* d_in, const int* in_sizes, int n_in,
                              void* d_out, int out_size)
{
    const float* x  = (const float*)d_in[0];
    const int*   ei = (const int*)  d_in[1];
    const float* ew = (const float*)d_in[2];
    const float* W0 = (const float*)d_in[3];
    const float* b0 = (const float*)d_in[4];
    const float* W1 = (const float*)d_in[5];
    const float* b1 = (const float*)d_in[6];
    float* out = (float*)d_out;

    int N = in_sizes[0] / FIN;
    int E = in_sizes[2];
    int total = E + N;

    int tpb = 256;
    int nblk = (N + tpb - 1) / tpb;
    int eblk = ((total + 1) / 2 + tpb - 1) / tpb;
    if (eblk > 4096) eblk = 4096;
    int sblk = (N + SCANB - 1) / SCANB;

    int dev = 0, nsm = 0, bpm = 0;
    cudaGetDevice(&dev);
    cudaDeviceGetAttribute(&nsm, cudaDevAttrMultiProcessorCount, dev);
    cudaOccupancyMaxActiveBlocksPerMultiprocessor(&bpm, prop_persist, tpb, 0);
    if (bpm < 1) bpm = 1;
    int pgrid = nsm * bpm;
    int maxuseful = (N + 15) / 16;
    if (pgrid > maxuseful) pgrid = maxuseful;

    // fork: MLP (independent of CSR build) on a side stream
    cudaStream_t s2;
    cudaStreamCreateWithFlags(&s2, cudaStreamNonBlocking);
    cudaEvent_t evFork, evJoin;
    cudaEventCreateWithFlags(&evFork, cudaEventDisableTiming);
    cudaEventCreateWithFlags(&evJoin, cudaEventDisableTiming);

    cudaEventRecord(evFork, 0);
    cudaStreamWaitEvent(s2, evFork, 0);
    mlp_kernel<<<(N + 127) / 128, 256, 0, s2>>>(x, W0, b0, W1, b1, N);
    cudaEventRecord(evJoin, s2);

    // CSR build on the main (capture) stream
    zero_kernel<<<nblk, tpb>>>(N);
    degcnt_kernel<<<eblk, tpb>>>(ei, ew, E, N);
    scan_fused<<<sblk, SCANB>>>(N, total, sblk);
    scatter_kernel<<<eblk, tpb>>>(ei, ew, E, N);

    cudaStreamWaitEvent(0, evJoin, 0);

    prop_persist<<<pgrid, tpb>>>(out, N, pgrid);
    // s2/events intentionally not destroyed: destroying objects referenced by
    // an in-progress capture invalidates the graph; leaks host handles only.
}

// round 15
// speedup vs baseline: 1.1848x; 1.1292x over previous
#include <cuda_runtime.h>
#include <cuda_fp16.h>

#define NMAX 100000
#define EMAX 3300000   // E + N self loops
#define FIN 512
#define HD  64
#define NITER 10
#define ALPHAF 0.1f
#define SCANB 1024
#define MAXBLK 128     // ceil(NMAX/SCANB) = 98

// ---------------- scratch (device globals; no allocation allowed) ------------
__device__ uint4 g_hv [NMAX * HD / 8];   // MLP output h (fp16); also z_0
__device__ uint4 g_z0v[NMAX * HD / 8];   // ping (fp16)
__device__ uint4 g_z1v[NMAX * HD / 8];   // pong (fp16)
__device__ float g_deg[NMAX];            // degree -> dinv (in place)
__device__ int   g_cnt[NMAX];            // in-degree histogram (by col)
__device__ int   g_rowptr[NMAX + 1];     // CSR row pointer (by destination)
__device__ int   g_cursor[NMAX];         // scatter cursors
__device__ int2  g_edge[EMAX];           // CSR: {src, bits of dinv[src]*w}
__device__ int   g_bsum[MAXBLK];         // block sums for scan
__device__ unsigned g_barcnt;            // prop grid-barrier counter
__device__ unsigned g_scanbar;           // scan grid-barrier counter
__device__ int   g_wcur[NITER];          // per-iteration work-steal cursors

// ---------------- preprocessing kernels --------------------------------------

__global__ void zero_kernel(int N) {
    int i = blockIdx.x * blockDim.x + threadIdx.x;
    int stride = gridDim.x * blockDim.x;
    if (i == 0) { g_barcnt = 0; g_scanbar = 0; }
    if (i < NITER) g_wcur[i] = 0;
    for (; i < N; i += stride) { g_deg[i] = 0.0f; g_cnt[i] = 0; }
}

__global__ void degcnt_kernel(const int* __restrict__ ei,
                              const float* __restrict__ ew, int E, int N) {
    int i2 = (blockIdx.x * blockDim.x + threadIdx.x) * 2;
    int stride = gridDim.x * blockDim.x * 2;
    int total = E + N;
    for (; i2 < total; i2 += stride) {
        #pragma unroll
        for (int q = 0; q < 2; q++) {
            int i = i2 + q;
            if (i >= total) break;
            int r, c; float w;
            if (i < E) { r = ei[i]; c = ei[E + i]; w = ew[i]; }
            else       { r = c = i - E; w = 1.0f; }
            atomicAdd(&g_deg[r], w);
            atomicAdd(&g_cnt[c], 1);
        }
    }
}

// ---- fused scan: dinv conversion + 3-phase exclusive scan in ONE kernel ------
__global__ void scan_fused(int N, int total, int nblk) {
    __shared__ int sdata[SCANB];
    __shared__ int bpref[MAXBLK];
    int tid = threadIdx.x;
    int bid = blockIdx.x;
    int i = bid * SCANB + tid;

    if (i < N) {
        float d = g_deg[i];
        g_deg[i] = (d > 0.0f) ? rsqrtf(d) : 0.0f;
    }
    int v = (i < N) ? g_cnt[i] : 0;
    sdata[tid] = v;
    __syncthreads();
    #pragma unroll
    for (int off = 1; off < SCANB; off <<= 1) {
        int t = (tid >= off) ? sdata[tid - off] : 0;
        __syncthreads();
        sdata[tid] += t;
        __syncthreads();
    }
    int local_excl = sdata[tid] - v;
    if (tid == SCANB - 1) g_bsum[bid] = sdata[tid];

    __syncthreads();
    if (tid == 0) {
        __threadfence();
        atomicAdd(&g_scanbar, 1u);
        while (atomicAdd(&g_scanbar, 0u) < (unsigned)nblk) __nanosleep(64);
    }
    __syncthreads();

    int bv = (tid < nblk) ? g_bsum[tid] : 0;
    if (tid < MAXBLK) bpref[tid] = bv;
    __syncthreads();
    #pragma unroll
    for (int off = 1; off < MAXBLK; off <<= 1) {
        int t = 0;
        if (tid < MAXBLK && tid >= off) t = bpref[tid - off];
        __syncthreads();
        if (tid < MAXBLK) bpref[tid] += t;
        __syncthreads();
    }
    int base = (bid > 0) ? bpref[bid - 1] : 0;

    if (i < N) {
        int r = local_excl + base;
        g_rowptr[i] = r;
        g_cursor[i] = r;
    }
    if (i == N - 1) g_rowptr[N] = total;
}

// store (src, dinv[src]*w) as int2; dinv[dst] applied once per node in prop
__global__ void scatter_kernel(const int* __restrict__ ei,
                               const float* __restrict__ ew, int E, int N) {
    int i2 = (blockIdx.x * blockDim.x + threadIdx.x) * 2;
    int stride = gridDim.x * blockDim.x * 2;
    int total = E + N;
    for (; i2 < total; i2 += stride) {
        #pragma unroll
        for (int q = 0; q < 2; q++) {
            int i = i2 + q;
            if (i >= total) break;
            int r, c; float w;
            if (i < E) { r = ei[i]; c = ei[E + i]; w = ew[i]; }
            else       { r = c = i - E; w = 1.0f; }
            float wn = g_deg[r] * w;          // g_deg holds dinv now
            int pos = atomicAdd(&g_cursor[c], 1);
            g_edge[pos] = make_int2(r, __float_as_int(wn));
        }
    }
}

// ---------------- MLP via tensor cores (mma.sync m16n8k16 f16->f32) ----------
// Stage 1 double-buffered (R14-proven).
#define AS_STRIDE 36
#define TS_STRIDE 68

__device__ __forceinline__ void mma16816(float c[4],
                                         unsigned a0, unsigned a1, unsigned a2, unsigned a3,
                                         unsigned b0, unsigned b1) {
    asm volatile(
        "mma.sync.aligned.m16n8k16.row.col.f32.f16.f16.f32 "
        "{%0,%1,%2,%3}, {%4,%5,%6,%7}, {%8,%9}, {%0,%1,%2,%3};"
        : "+f"(c[0]), "+f"(c[1]), "+f"(c[2]), "+f"(c[3])
        : "r"(a0), "r"(a1), "r"(a2), "r"(a3), "r"(b0), "r"(b1));
}

__global__ __launch_bounds__(256) void mlp_kernel(
    const float* __restrict__ x,  const float* __restrict__ W0,
    const float* __restrict__ b0, const float* __restrict__ W1,
    const float* __restrict__ b1, int N)
{
    __shared__ __half As[2][128][AS_STRIDE];
    __shared__ __half Bs[2][64][AS_STRIDE];
    __shared__ __half Ts[128][TS_STRIDE];
    __shared__ __half W1s[64][TS_STRIDE];
    __shared__ float b0s[64];
    __shared__ float b1s[64];

    int tid  = threadIdx.x;
    int wid  = tid >> 5;
    int lane = tid & 31;
    int g = lane >> 2;
    int t = lane & 3;
    int wr0 = wid * 16;
    int row0 = blockIdx.x * 128;

    for (int i = tid; i < 64 * 64; i += 256) {
        int k = i >> 6, n = i & 63;
        W1s[n][k] = __float2half(W1[i]);
    }
    if (tid < 64) { b0s[tid] = b0[tid]; b1s[tid] = b1[tid]; }

    float c1a[8][4] = {};

    int lr = tid >> 1;
    int lq = tid & 1;
    bool rowok = (row0 + lr) < N;
    const float* xrow = x + (size_t)(row0 + lr) * FIN;
    int wkr = tid >> 6;
    int wnc = tid & 63;

    float4 xreg[4];
    float  wreg[8];

    #pragma unroll
    for (int jj = 0; jj < 4; jj++)
        xreg[jj] = rowok ? *(const float4*)(xrow + 16 * lq + 4 * jj)
                         : make_float4(0.f, 0.f, 0.f, 0.f);
    #pragma unroll
    for (int q = 0; q < 8; q++)
        wreg[q] = W0[(size_t)(wkr + 4 * q) * HD + wnc];

    #pragma unroll
    for (int jj = 0; jj < 4; jj++) {
        *(__half2*)&As[0][lr][16 * lq + 4 * jj]     = __floats2half2_rn(xreg[jj].x, xreg[jj].y);
        *(__half2*)&As[0][lr][16 * lq + 4 * jj + 2] = __floats2half2_rn(xreg[jj].z, xreg[jj].w);
    }
    #pragma unroll
    for (int q = 0; q < 8; q++)
        Bs[0][wnc][wkr + 4 * q] = __float2half(wreg[q]);
    __syncthreads();

    #pragma unroll 1
    for (int c = 0; c < FIN / 32; c++) {
        int buf = c & 1;
        if (c + 1 < FIN / 32) {
            int k0 = (c + 1) * 32;
            #pragma unroll
            for (int jj = 0; jj < 4; jj++)
                xreg[jj] = rowok ? *(const float4*)(xrow + k0 + 16 * lq + 4 * jj)
                                 : make_float4(0.f, 0.f, 0.f, 0.f);
            #pragma unroll
            for (int q = 0; q < 8; q++)
                wreg[q] = W0[(size_t)(k0 + wkr + 4 * q) * HD + wnc];
        }

        #pragma unroll
        for (int kk = 0; kk < 32; kk += 16) {
            unsigned a0 = *(const unsigned*)&As[buf][wr0 + g][kk + 2 * t];
            unsigned a1 = *(const unsigned*)&As[buf][wr0 + g + 8][kk + 2 * t];
            unsigned a2 = *(const unsigned*)&As[buf][wr0 + g][kk + 2 * t + 8];
            unsigned a3 = *(const unsigned*)&As[buf][wr0 + g + 8][kk + 2 * t + 8];
            #pragma unroll
            for (int nt = 0; nt < 8; nt++) {
                unsigned bb0 = *(const unsigned*)&Bs[buf][nt * 8 + g][kk + 2 * t];
                unsigned bb1 = *(const unsigned*)&Bs[buf][nt * 8 + g][kk + 2 * t + 8];
                mma16816(c1a[nt], a0, a1, a2, a3, bb0, bb1);
            }
        }

        if (c + 1 < FIN / 32) {
            int nbuf = buf ^ 1;
            #pragma unroll
            for (int jj = 0; jj < 4; jj++) {
                *(__half2*)&As[nbuf][lr][16 * lq + 4 * jj]     = __floats2half2_rn(xreg[jj].x, xreg[jj].y);
                *(__half2*)&As[nbuf][lr][16 * lq + 4 * jj + 2] = __floats2half2_rn(xreg[jj].z, xreg[jj].w);
            }
            #pragma unroll
            for (int q = 0; q < 8; q++)
                Bs[nbuf][wnc][wkr + 4 * q] = __float2half(wreg[q]);
        }
        __syncthreads();
    }

    #pragma unroll
    for (int nt = 0; nt < 8; nt++) {
        int col = nt * 8 + 2 * t;
        float v0 = fmaxf(c1a[nt][0] + b0s[col], 0.f);
        float v1 = fmaxf(c1a[nt][1] + b0s[col + 1], 0.f);
        float v2 = fmaxf(c1a[nt][2] + b0s[col], 0.f);
        float v3 = fmaxf(c1a[nt][3] + b0s[col + 1], 0.f);
        *(__half2*)&Ts[wr0 + g][col]     = __floats2half2_rn(v0, v1);
        *(__half2*)&Ts[wr0 + g + 8][col] = __floats2half2_rn(v2, v3);
    }
    __syncthreads();

    float c2a[8][4] = {};
    #pragma unroll
    for (int kk = 0; kk < 64; kk += 16) {
        unsigned a0 = *(const unsigned*)&Ts[wr0 + g][kk + 2 * t];
        unsigned a1 = *(const unsigned*)&Ts[wr0 + g + 8][kk + 2 * t];
        unsigned a2 = *(const unsigned*)&Ts[wr0 + g][kk + 2 * t + 8];
        unsigned a3 = *(const unsigned*)&Ts[wr0 + g + 8][kk + 2 * t + 8];
        #pragma unroll
        for (int nt = 0; nt < 8; nt++) {
            unsigned bb0 = *(const unsigned*)&W1s[nt * 8 + g][kk + 2 * t];
            unsigned bb1 = *(const unsigned*)&W1s[nt * 8 + g][kk + 2 * t + 8];
            mma16816(c2a[nt], a0, a1, a2, a3, bb0, bb1);
        }
    }

    __half* gh = (__half*)g_hv;
    int r0 = row0 + wr0 + g;
    int r1 = r0 + 8;
    #pragma unroll
    for (int nt = 0; nt < 8; nt++) {
        int col = nt * 8 + 2 * t;
        __half2 lo = __floats2half2_rn(c2a[nt][0] + b1s[col], c2a[nt][1] + b1s[col + 1]);
        __half2 hi = __floats2half2_rn(c2a[nt][2] + b1s[col], c2a[nt][3] + b1s[col + 1]);
        if (r0 < N) *(__half2*)(gh + (size_t)r0 * HD + col) = lo;
        if (r1 < N) *(__half2*)(gh + (size_t)r1 * HD + col) = hi;
    }
}

// ---------------- persistent propagation with dynamic work stealing -----------
// Per-iteration atomic cursor: blocks grab 16 nodes at a time, so all blocks
// finish within one chunk of each other -> grid-barrier wait ~ 0.
__global__ __launch_bounds__(256) void prop_persist(float* __restrict__ dout,
                                                    int N, int nblocks)
{
    int tid  = threadIdx.x;
    int lane = tid & 15;
    int lwid = tid >> 4;
    const __half* gh = (const __half*)g_hv;
    __shared__ int sbase;

    #pragma unroll 1
    for (int it = 0; it < NITER; it++) {
        const __half* zin = (it == 0) ? gh
                           : (const __half*)((it & 1) ? g_z0v : g_z1v);
        __half* zout16 = (__half*)((it & 1) ? g_z1v : g_z0v);

        for (;;) {
            if (tid == 0) sbase = atomicAdd(&g_wcur[it], 16);
            __syncthreads();
            int base = sbase;
            __syncthreads();          // protect sbase before next overwrite
            if (base >= N) break;
            int node = base + lwid;
            if (node < N) {
                int start = __ldg(&g_rowptr[node]);
                int end   = __ldg(&g_rowptr[node + 1]);

                float acc[4] = {};
                int e = start;
                for (; e + 4 <= end; e += 4) {
                    int2 ea = __ldg(&g_edge[e]);
                    int2 eb = __ldg(&g_edge[e + 1]);
                    int2 ec = __ldg(&g_edge[e + 2]);
                    int2 ed = __ldg(&g_edge[e + 3]);
                    uint2 va = __ldcg((const uint2*)(zin + (size_t)ea.x * HD + 4 * lane));
                    uint2 vb = __ldcg((const uint2*)(zin + (size_t)eb.x * HD + 4 * lane));
                    uint2 vc = __ldcg((const uint2*)(zin + (size_t)ec.x * HD + 4 * lane));
                    uint2 vd = __ldcg((const uint2*)(zin + (size_t)ed.x * HD + 4 * lane));
                    float wa = __int_as_float(ea.y), wb = __int_as_float(eb.y);
                    float wc = __int_as_float(ec.y), wd = __int_as_float(ed.y);
                    float2 a0 = __half22float2(*(__half2*)&va.x);
                    float2 a1 = __half22float2(*(__half2*)&va.y);
                    float2 b0 = __half22float2(*(__half2*)&vb.x);
                    float2 b1 = __half22float2(*(__half2*)&vb.y);
                    float2 c0 = __half22float2(*(__half2*)&vc.x);
                    float2 c1 = __half22float2(*(__half2*)&vc.y);
                    float2 d0 = __half22float2(*(__half2*)&vd.x);
                    float2 d1 = __half22float2(*(__half2*)&vd.y);
                    acc[0] += wa * a0.x + wb * b0.x + wc * c0.x + wd * d0.x;
                    acc[1] += wa * a0.y + wb * b0.y + wc * c0.y + wd * d0.y;
                    acc[2] += wa * a1.x + wb * b1.x + wc * c1.x + wd * d1.x;
                    acc[3] += wa * a1.y + wb * b1.y + wc * c1.y + wd * d1.y;
                }
                for (; e < end; e++) {
                    int2 ea = __ldg(&g_edge[e]);
                    uint2 va = __ldcg((const uint2*)(zin + (size_t)ea.x * HD + 4 * lane));
                    float wa = __int_as_float(ea.y);
                    float2 a0 = __half22float2(*(__half2*)&va.x);
                    float2 a1 = __half22float2(*(__half2*)&va.y);
                    acc[0] += wa * a0.x;
                    acc[1] += wa * a0.y;
                    acc[2] += wa * a1.x;
                    acc[3] += wa * a1.y;
                }

                float s = (1.0f - ALPHAF) * __ldg(&g_deg[node]);

                uint2 hv = __ldg((const uint2*)(gh + (size_t)node * HD + 4 * lane));
                float2 h0 = __half22float2(*(__half2*)&hv.x);
                float2 h1 = __half22float2(*(__half2*)&hv.y);
                float o0 = s * acc[0] + ALPHAF * h0.x;
                float o1 = s * acc[1] + ALPHAF * h0.y;
                float o2 = s * acc[2] + ALPHAF * h1.x;
                float o3 = s * acc[3] + ALPHAF * h1.y;

                if (it == NITER - 1) {
                    *(float4*)(dout + (size_t)node * HD + 4 * lane) =
                        make_float4(o0, o1, o2, o3);
                } else {
                    __half2 p0 = __float22half2_rn(make_float2(o0, o1));
                    __half2 p1 = __float22half2_rn(make_float2(o2, o3));
                    uint2 u;
                    u.x = *(unsigned int*)&p0;
                    u.y = *(unsigned int*)&p1;
                    *(uint2*)(zout16 + (size_t)node * HD + 4 * lane) = u;
                }
            }
        }

        if (it < NITER - 1) {
            __syncthreads();
            if (tid == 0) {
                __threadfence();
                atomicAdd(&g_barcnt, 1u);
                unsigned target = (unsigned)(it + 1) * (unsigned)nblocks;
                while (atomicAdd(&g_barcnt, 0u) < target) __nanosleep(128);
            }
            __syncthreads();
        }
    }
}

// ---------------- launcher ----------------------------------------------------
extern "C" void kernel_launch(void* const* d_in, const int* in_sizes, int n_in,
                              void* d_out, int out_size)
{
    const float* x  = (const float*)d_in[0];
    const int*   ei = (const int*)  d_in[1];
    const float* ew = (const float*)d_in[2];
    const float* W0 = (const float*)d_in[3];
    const float* b0 = (const float*)d_in[4];
    const float* W1 = (const float*)d_in[5];
    const float* b1 = (const float*)d_in[6];
    float* out = (float*)d_out;

    int N = in_sizes[0] / FIN;
    int E = in_sizes[2];
    int total = E + N;

    int tpb = 256;
    int nblk = (N + tpb - 1) / tpb;
    int eblk = ((total + 1) / 2 + tpb - 1) / tpb;
    if (eblk > 4096) eblk = 4096;
    int sblk = (N + SCANB - 1) / SCANB;

    int dev = 0, nsm = 0, bpm = 0;
    cudaGetDevice(&dev);
    cudaDeviceGetAttribute(&nsm, cudaDevAttrMultiProcessorCount, dev);
    cudaOccupancyMaxActiveBlocksPerMultiprocessor(&bpm, prop_persist, tpb, 0);
    if (bpm < 1) bpm = 1;
    int pgrid = nsm * bpm;
    int maxuseful = (N + 15) / 16;
    if (pgrid > maxuseful) pgrid = maxuseful;

    // fork: MLP (independent of CSR build) on a side stream
    cudaStream_t s2;
    cudaStreamCreateWithFlags(&s2, cudaStreamNonBlocking);
    cudaEvent_t evFork, evJoin;
    cudaEventCreateWithFlags(&evFork, cudaEventDisableTiming);
    cudaEventCreateWithFlags(&evJoin, cudaEventDisableTiming);

    cudaEventRecord(evFork, 0);
    cudaStreamWaitEvent(s2, evFork, 0);
    mlp_kernel<<<(N + 127) / 128, 256, 0, s2>>>(x, W0, b0, W1, b1, N);
    cudaEventRecord(evJoin, s2);

    // CSR build on the main (capture) stream
    zero_kernel<<<nblk, tpb>>>(N);
    degcnt_kernel<<<eblk, tpb>>>(ei, ew, E, N);
    scan_fused<<<sblk, SCANB>>>(N, total, sblk);
    scatter_kernel<<<eblk, tpb>>>(ei, ew, E, N);

    cudaStreamWaitEvent(0, evJoin, 0);

    prop_persist<<<pgrid, tpb>>>(out, N, pgrid);
    // s2/events intentionally not destroyed: destroying objects referenced by
    // an in-progress capture invalidates the graph; leaks host handles only.
}